// round 10
// baseline (speedup 1.0000x reference)
#include <cuda_runtime.h>
#include <cuda_fp16.h>
#include <cstdint>
#include <math.h>

#define HH 128
#define WWD 128
#define HWP (HH*WWD)
#define BB 2

// ---------------- device scratch ----------------
__device__ __half g_nhwc_h[BB*HWP*64]; // 4 MB, input in NHWC (fp16)
__device__ float g_pooled[BB*64];      // per (b,c) plane sums
__device__ float g_Mg[8*81];           // 8 tap-transform matrices (9x9)
__device__ __half g_wtf[9*4*32*32];    // W in per-lane fragment stream [slab][n0i][lane][32 halves]

#define SMV 0.20710678118654746f
#define M2V 0.08578643762690495f
__device__ const float c_Mbase[81] = {
    0.5f, SMV , 0.f , SMV , M2V , 0.f , 0.f , 0.f , 0.f ,
    0.f , 1.f , 0.f , 0.f , 0.f , 0.f , 0.f , 0.f , 0.f ,
    0.f , SMV , 0.5f, 0.f , M2V , SMV , 0.f , 0.f , 0.f ,
    0.f , 0.f , 0.f , 1.f , 0.f , 0.f , 0.f , 0.f , 0.f ,
    0.f , 0.f , 0.f , 0.f , 1.f , 0.f , 0.f , 0.f , 0.f ,
    0.f , 0.f , 0.f , 0.f , 0.f , 1.f , 0.f , 0.f , 0.f ,
    0.f , 0.f , 0.f , SMV , M2V , 0.f , 0.5f, SMV , 0.f ,
    0.f , 0.f , 0.f , 0.f , 0.f , 0.f , 0.f , 1.f , 0.f ,
    0.f , 0.f , 0.f , 0.f , M2V , SMV , 0.f , SMV , 0.5f
};

__device__ const int c_P2[8][9] = {
    {0,1,2,3,4,5,6,7,8},
    {3,0,1,6,4,2,7,8,5},
    {6,3,0,7,4,1,8,5,2},
    {7,6,3,8,4,0,5,2,1},
    {8,7,6,5,4,3,2,1,0},
    {5,8,7,2,4,6,1,0,3},
    {2,5,8,1,4,7,0,3,6},
    {1,2,5,0,4,8,3,6,7}
};

// ---------------- kernel 1: NCHW -> NHWC transpose (fp32 -> fp16) ----------------
__global__ __launch_bounds__(256) void nhwc_kernel(const float* __restrict__ in) {
    __shared__ float tile[64][33];
    int bid = blockIdx.x;
    int b   = bid >> 9;
    int rem = bid & 511;
    int y   = rem >> 2;
    int x0  = (rem & 3) << 5;
    int t   = threadIdx.x;

    int xl = t & 31, cb = t >> 5;
    #pragma unroll
    for (int i = 0; i < 8; i++) {
        int c = cb + i*8;
        tile[c][xl] = in[(((b*64 + c)*128 + y)*128) + x0 + xl];
    }
    __syncthreads();
    int c2 = t & 63, xb = t >> 6;
    #pragma unroll
    for (int i = 0; i < 8; i++) {
        int x = xb + i*4;
        g_nhwc_h[(((b*128 + y)*128) + x0 + x)*64 + c2] = __float2half_rn(tile[c2][x]);
    }
}

// ---------------- kernel 2: per-(b,c) plane sums ----------------
__global__ __launch_bounds__(256) void pool_kernel(const float* __restrict__ in) {
    __shared__ float red[8];
    int bc = blockIdx.x, t = threadIdx.x;
    const float* p = in + (size_t)bc * HWP;
    float s = 0.f;
    for (int i = t; i < HWP; i += 256) s += p[i];
    #pragma unroll
    for (int o = 16; o > 0; o >>= 1) s += __shfl_down_sync(0xffffffffu, s, o);
    if ((t & 31) == 0) red[t >> 5] = s;
    __syncthreads();
    if (t == 0) {
        float tot = 0.f;
        #pragma unroll
        for (int i = 0; i < 8; i++) tot += red[i];
        g_pooled[bc] = tot;
    }
}

// ---------------- kernel 3: W fragment stream (blocks 0..143) + setup (block 144) ----------------
// g_wtf flat index f = slab*4096 + n0i*1024 + lane*32 + e
//   e = j*16 + s*4 + pair*2 + within
//   o  = n0i*16 + j*8 + (lane>>2)
//   ch = 2*(lane&3) + 16*s + 8*pair + within      (ch = within-slab channel c)
//   value = weight[o][c=ch][k2=slab]  (weight layout o*576 + c*9 + k2)
__global__ __launch_bounds__(256) void wtsetup_kernel(const float* __restrict__ w,
                                                      const float* __restrict__ fc_w,
                                                      const float* __restrict__ fc_b) {
    int t = threadIdx.x;
    if (blockIdx.x < 144) {
        int f = blockIdx.x*256 + t;            // 36864 elements
        int e    = f & 31;
        int lane = (f >> 5) & 31;
        int n0i  = (f >> 10) & 3;
        int slab = f >> 12;
        int j = e >> 4, r = e & 15;
        int s = r >> 2, pair = (r >> 1) & 1, within = r & 1;
        int g = lane >> 2, tq = lane & 3;
        int o  = n0i*16 + j*8 + g;
        int ch = 2*tq + 16*s + 8*pair + within;
        g_wtf[f] = __float2half_rn(w[o*576 + ch*9 + slab]);
    } else {
        __shared__ float r_s[4];
        if (t < 128) {                          // warp per fc row, lane per 2 channels
            int t4 = t >> 5, l = t & 31;
            const float inv = 1.f / (float)HWP;
            float p0 = (g_pooled[2*l]   + g_pooled[64 + 2*l])   * inv;
            float p1 = (g_pooled[2*l+1] + g_pooled[64 + 2*l+1]) * inv;
            float s = p0 * fc_w[t4*64 + 2*l] + p1 * fc_w[t4*64 + 2*l+1];
            #pragma unroll
            for (int o = 16; o > 0; o >>= 1) s += __shfl_down_sync(0xffffffffu, s, o);
            if (l == 0) r_s[t4] = 1.f / (1.f + expf(-(s + fc_b[t4])));
        }
        __syncthreads();
        for (int e = t; e < 648; e += 256) {
            int g = e / 81, kk = e % 81;
            int k = kk / 9, k2 = kk % 9;
            int pk = c_P2[g][k];
            float mb = c_Mbase[pk*9 + k2];
            float v;
            if ((g & 1) == 0) {
                float rr = r_s[g >> 1];
                v = rr * mb + (1.f - rr) * ((k2 == pk) ? 1.f : 0.f);
            } else {
                v = mb;
            }
            g_Mg[e] = v;
        }
    }
}

// ---------------- kernel 4: fused DCN (sample + transform + fp16 MMA GEMM) ----------------
// smem layout (float units), total 16008 floats = 64032 B:
//   U half[32 px][584]   @ 0      (9344 floats)  row = 9 slabs x 64 halves + 8 pad halves
//   A_s [32][9][12]      @ 9344   (3584)   (phase0/1) -- aliased by outb[64][33] in epilogue
//   idx_s[32*9][4] int   @ 12928  (1152)
//   wgt_s[32*9][4]       @ 14080  (1152)
//   wc8T[8][33]          @ 15232  (264)
//   bias_s[512]          @ 15496  (512)
#define USTRH    584
#define A_OFF    9344
#define IDX_OFF  12928
#define WGT_OFF  14080
#define OUTB_OFF 9344
#define WC8_OFF  15232
#define BIAS_OFF 15496
#define SMEM_FLOATS 16008
#define SMEM_BYTES  (SMEM_FLOATS*4)

__global__ __launch_bounds__(256, 3) void main_kernel(
    const float* __restrict__ offset, const float* __restrict__ mask,
    const float* __restrict__ wc8g,   const float* __restrict__ bias,
    float* __restrict__ out)
{
    extern __shared__ float sm[];
    __half* u_h  = (__half*)sm;
    float* A_s   = sm + A_OFF;
    int*   idx_s = (int*)(sm + IDX_OFF);
    float* wgt_s = sm + WGT_OFF;
    float* outb  = sm + OUTB_OFF;
    float* wc8T  = sm + WC8_OFF;
    float* bias_s= sm + BIAS_OFF;

    int t     = threadIdx.x;
    int bid   = blockIdx.x;               // 1024: b(2) * 512 tiles
    int b     = bid >> 9;
    int tbase = (bid & 511) << 5;
    int h     = tbase >> 7;
    int w0    = tbase & 127;
    int w     = t >> 5;
    int l     = t & 31;

    // ---- phase 0a: wc8 (transposed), bias staging ----
    wc8T[w*33 + l] = wc8g[((b*8 + w) << 14) + tbase + l];
    bias_s[t]       = bias[t];
    bias_s[t + 256] = bias[t + 256];

    // ---- phase 0b: bilinear indices & weights (mask folded) ----
    for (int task = t; task < 288; task += 256) {
        int p = task & 31, k = task >> 5;
        int pix = tbase + p;
        float offy = offset[((b*18 + 2*k    ) << 14) + pix];
        float offx = offset[((b*18 + 2*k + 1) << 14) + pix];
        float mval = mask  [((b*9  + k      ) << 14) + pix];
        float py = (float)h        + (float)(k/3) - 1.f + offy;
        float px = (float)(w0 + p) + (float)(k%3) - 1.f + offx;
        float y0f = floorf(py), x0f = floorf(px);
        float ly = py - y0f, lx = px - x0f;
        int y0 = (int)y0f, x0i = (int)x0f;
        int y1 = y0 + 1, x1 = x0i + 1;
        bool vy0 = (y0 >= 0) & (y0 <= 127);
        bool vy1 = (y1 >= 0) & (y1 <= 127);
        bool vx0 = (x0i >= 0) & (x0i <= 127);
        bool vx1 = (x1 >= 0) & (x1 <= 127);
        float w00 = (1.f-ly)*(1.f-lx) * ((vy0 & vx0) ? mval : 0.f);
        float w01 = (1.f-ly)*lx       * ((vy0 & vx1) ? mval : 0.f);
        float w10 = ly*(1.f-lx)       * ((vy1 & vx0) ? mval : 0.f);
        float w11 = ly*lx             * ((vy1 & vx1) ? mval : 0.f);
        int cy0 = min(max(y0, 0), 127), cy1 = min(max(y1, 0), 127);
        int cx0 = min(max(x0i,0), 127), cx1 = min(max(x1, 0), 127);
        int b4 = (p*9 + k)*4;
        idx_s[b4+0] = cy0*128 + cx0;
        idx_s[b4+1] = cy0*128 + cx1;
        idx_s[b4+2] = cy1*128 + cx0;
        idx_s[b4+3] = cy1*128 + cx1;
        wgt_s[b4+0] = w00; wgt_s[b4+1] = w01; wgt_s[b4+2] = w10; wgt_s[b4+3] = w11;
    }
    __syncthreads();

    // ---- phase 0c: A[p][k][k2] = sum_g wc8[g] * M_g ----
    for (int e = t; e < 2592; e += 256) {
        int p = e & 31, kk = e >> 5;
        int k = kk / 9, k2 = kk - k*9;
        float a = 0.f;
        #pragma unroll
        for (int g = 0; g < 8; g++) a += wc8T[g*33 + p] * g_Mg[g*81 + kk];
        A_s[p*112 + k*12 + k2] = a;
    }
    __syncthreads();

    // ---- phase 1: gather (fp16) + bilinear + tap transform -> u_h (fp16, permuted pos) ----
    {
        const __half2* ib = (const __half2*)g_nhwc_h + ((size_t)b << 19);  // b * 16384 * 32 half2
        const int4*   idx4 = (const int4*)idx_s;
        const float4* wgt4 = (const float4*)wgt_s;
        // pos of channel 2l within a slab's 64 halves (within=0; 2l+1 is pos+1)
        int pos = (l & 3)*16 + (l >> 3)*4 + ((l >> 2) & 1)*2;
        #pragma unroll
        for (int pp = 0; pp < 4; pp++) {
            int p = w*4 + pp;
            float2 ua[9];
            #pragma unroll
            for (int i = 0; i < 9; i++) { ua[i].x = 0.f; ua[i].y = 0.f; }
            #pragma unroll
            for (int k = 0; k < 9; k++) {
                int4   id = idx4[p*9 + k];
                float4 wg = wgt4[p*9 + k];
                float2 c00 = __half22float2(ib[id.x*32 + l]);
                float2 c01 = __half22float2(ib[id.y*32 + l]);
                float2 c10 = __half22float2(ib[id.z*32 + l]);
                float2 c11 = __half22float2(ib[id.w*32 + l]);
                float vx = wg.x*c00.x + wg.y*c01.x + wg.z*c10.x + wg.w*c11.x;
                float vy = wg.x*c00.y + wg.y*c01.y + wg.z*c10.y + wg.w*c11.y;
                const float* Ab = A_s + p*112 + k*12;
                float4 a0 = *(const float4*)(Ab);
                float4 a1 = *(const float4*)(Ab + 4);
                float  a8 = Ab[8];
                ua[0].x += a0.x*vx; ua[0].y += a0.x*vy;
                ua[1].x += a0.y*vx; ua[1].y += a0.y*vy;
                ua[2].x += a0.z*vx; ua[2].y += a0.z*vy;
                ua[3].x += a0.w*vx; ua[3].y += a0.w*vy;
                ua[4].x += a1.x*vx; ua[4].y += a1.x*vy;
                ua[5].x += a1.y*vx; ua[5].y += a1.y*vy;
                ua[6].x += a1.z*vx; ua[6].y += a1.z*vy;
                ua[7].x += a1.w*vx; ua[7].y += a1.w*vy;
                ua[8].x += a8  *vx; ua[8].y += a8  *vy;
            }
            __half* urow = u_h + p*USTRH;
            #pragma unroll
            for (int k2 = 0; k2 < 9; k2++) {
                *(__half2*)(urow + k2*64 + pos) = __floats2half2_rn(ua[k2].x, ua[k2].y);
            }
        }
    }
    __syncthreads();

    // ---- phase 2: fp16 MMA  D[32px x 64o] = u[32 x 576] * W[576 x 64]  (no barriers) ----
    // warp w: px rows m0..m0+15 (m0=(w&1)*16), o cols n0i*16..+15 (n0i=w>>1)
    int m0  = (w & 1) * 16;
    int n0i = w >> 1;
    int g   = l >> 2;
    int tq  = l & 3;
    const __half* uR0 = u_h + (m0 + g)*USTRH + tq*16;
    const __half* uR1 = uR0 + 8*USTRH;
    const __half* Bb  = g_wtf + (n0i*32 + l)*32;

    float acc[2][4];
    #pragma unroll
    for (int j = 0; j < 2; j++)
        #pragma unroll
        for (int i = 0; i < 4; i++) acc[j][i] = 0.f;

    #pragma unroll
    for (int ch = 0; ch < 9; ch++) {
        uint32_t Ag0[8], Ag1[8], Bw[16];
        *(uint4*)(Ag0)     = *(const uint4*)(uR0 + ch*64);
        *(uint4*)(Ag0 + 4) = *(const uint4*)(uR0 + ch*64 + 8);
        *(uint4*)(Ag1)     = *(const uint4*)(uR1 + ch*64);
        *(uint4*)(Ag1 + 4) = *(const uint4*)(uR1 + ch*64 + 8);
        const uint4* Bp = (const uint4*)(Bb + ch*4096);
        *(uint4*)(Bw)      = Bp[0];
        *(uint4*)(Bw + 4)  = Bp[1];
        *(uint4*)(Bw + 8)  = Bp[2];
        *(uint4*)(Bw + 12) = Bp[3];
        #pragma unroll
        for (int s = 0; s < 4; s++) {
            uint32_t a0 = Ag0[s*2], a2 = Ag0[s*2+1];
            uint32_t a1 = Ag1[s*2], a3 = Ag1[s*2+1];
            #pragma unroll
            for (int j = 0; j < 2; j++) {
                uint32_t b0 = Bw[j*8 + s*2], b1 = Bw[j*8 + s*2 + 1];
                asm volatile(
                    "mma.sync.aligned.m16n8k16.row.col.f32.f16.f16.f32 "
                    "{%0,%1,%2,%3}, {%4,%5,%6,%7}, {%8,%9}, {%0,%1,%2,%3};\n"
                    : "+f"(acc[j][0]), "+f"(acc[j][1]), "+f"(acc[j][2]), "+f"(acc[j][3])
                    : "r"(a0), "r"(a1), "r"(a2), "r"(a3), "r"(b0), "r"(b1));
            }
        }
    }

    // ---- epilogue: stage D in smem (outb[o][px]), coalesced NCHW store + bias ----
    __syncthreads();
    #pragma unroll
    for (int j = 0; j < 2; j++) {
        int o = n0i*16 + j*8 + 2*tq;
        outb[(o    )*33 + m0 + g    ] = acc[j][0];
        outb[(o + 1)*33 + m0 + g    ] = acc[j][1];
        outb[(o    )*33 + m0 + g + 8] = acc[j][2];
        outb[(o + 1)*33 + m0 + g + 8] = acc[j][3];
    }
    __syncthreads();
    #pragma unroll
    for (int r = 0; r < 8; r++) {
        int o = r*8 + w;       // constant per warp
        int p = l;
        float be = 0.f;
        #pragma unroll
        for (int gg = 0; gg < 8; gg++) be += wc8T[gg*33 + p] * bias_s[gg*64 + o];
        out[((b*64 + o) << 14) + tbase + p] = outb[o*33 + p] + be;
    }
}

// ---------------- launch ----------------
extern "C" void kernel_launch(void* const* d_in, const int* in_sizes, int n_in,
                              void* d_out, int out_size) {
    const float* input  = (const float*)d_in[0];
    const float* offset = (const float*)d_in[1];
    const float* maskp  = (const float*)d_in[2];
    const float* w_c8   = (const float*)d_in[3];
    const float* weight = (const float*)d_in[4];
    const float* bias   = (const float*)d_in[5];
    const float* fc_w   = (const float*)d_in[6];
    const float* fc_b   = (const float*)d_in[7];
    float* out = (float*)d_out;

    cudaFuncSetAttribute(main_kernel, cudaFuncAttributeMaxDynamicSharedMemorySize, SMEM_BYTES);

    nhwc_kernel   <<<1024, 256>>>(input);
    pool_kernel   <<<128, 256>>>(input);
    wtsetup_kernel<<<145, 256>>>(weight, fc_w, fc_b);
    main_kernel   <<<1024, 256, SMEM_BYTES>>>(offset, maskp, w_c8, bias, out);
}

// round 11
// speedup vs baseline: 1.5800x; 1.5800x over previous
#include <cuda_runtime.h>
#include <cuda_fp16.h>
#include <cstdint>
#include <math.h>

#define HH 128
#define WWD 128
#define HWP (HH*WWD)
#define BB 2

// ---------------- device scratch ----------------
__device__ __half g_nhwc_h[BB*HWP*64]; // 4 MB, input in NHWC (fp16)
__device__ float g_pooled[BB*64];      // per (b,c) plane sums (atomic; zero-init, re-zeroed each call)
__device__ float g_Mg[8*81];           // 8 tap-transform matrices (9x9)
__device__ __half g_wtf[9*4*32*32];    // W in per-lane fragment stream [slab][n0i][lane][32 halves]

#define SMV 0.20710678118654746f
#define M2V 0.08578643762690495f
__device__ const float c_Mbase[81] = {
    0.5f, SMV , 0.f , SMV , M2V , 0.f , 0.f , 0.f , 0.f ,
    0.f , 1.f , 0.f , 0.f , 0.f , 0.f , 0.f , 0.f , 0.f ,
    0.f , SMV , 0.5f, 0.f , M2V , SMV , 0.f , 0.f , 0.f ,
    0.f , 0.f , 0.f , 1.f , 0.f , 0.f , 0.f , 0.f , 0.f ,
    0.f , 0.f , 0.f , 0.f , 1.f , 0.f , 0.f , 0.f , 0.f ,
    0.f , 0.f , 0.f , 0.f , 0.f , 1.f , 0.f , 0.f , 0.f ,
    0.f , 0.f , 0.f , SMV , M2V , 0.f , 0.5f, SMV , 0.f ,
    0.f , 0.f , 0.f , 0.f , 0.f , 0.f , 0.f , 1.f , 0.f ,
    0.f , 0.f , 0.f , 0.f , M2V , SMV , 0.f , SMV , 0.5f
};

__device__ const int c_P2[8][9] = {
    {0,1,2,3,4,5,6,7,8},
    {3,0,1,6,4,2,7,8,5},
    {6,3,0,7,4,1,8,5,2},
    {7,6,3,8,4,0,5,2,1},
    {8,7,6,5,4,3,2,1,0},
    {5,8,7,2,4,6,1,0,3},
    {2,5,8,1,4,7,0,3,6},
    {1,2,5,0,4,8,3,6,7}
};

// ---------------- kernel 1: NCHW -> NHWC transpose (fp32 -> fp16) + pooled sums ----------------
__global__ __launch_bounds__(256) void nhwc_kernel(const float* __restrict__ in) {
    __shared__ float tile[64][33];
    int bid = blockIdx.x;
    int b   = bid >> 9;
    int rem = bid & 511;
    int y   = rem >> 2;
    int x0  = (rem & 3) << 5;
    int t   = threadIdx.x;

    int xl = t & 31, cb = t >> 5;
    #pragma unroll
    for (int i = 0; i < 8; i++) {
        int c = cb + i*8;
        tile[c][xl] = in[(((b*64 + c)*128 + y)*128) + x0 + xl];
    }
    __syncthreads();
    int c2 = t & 63, xb = t >> 6;
    #pragma unroll
    for (int i = 0; i < 8; i++) {
        int x = xb + i*4;
        g_nhwc_h[(((b*128 + y)*128) + x0 + x)*64 + c2] = __float2half_rn(tile[c2][x]);
    }
    // pooled channel sums for this (b, y, x-chunk): accumulate atomically
    if (t < 64) {
        float s = 0.f;
        #pragma unroll
        for (int x = 0; x < 32; x++) s += tile[t][x];
        atomicAdd(&g_pooled[b*64 + t], s);
    }
}

// ---------------- kernel 3: W fragment stream (blocks 0..143) + setup (block 144) ----------------
// g_wtf flat index f = slab*4096 + n0i*1024 + lane*32 + e
//   e = j*16 + s*4 + pair*2 + within
//   o  = n0i*16 + j*8 + (lane>>2)
//   ch = 2*(lane&3) + 16*s + 8*pair + within      (ch = within-slab channel c)
//   value = weight[o][c=ch][k2=slab]  (weight layout o*576 + c*9 + k2)
__global__ __launch_bounds__(256) void wtsetup_kernel(const float* __restrict__ w,
                                                      const float* __restrict__ fc_w,
                                                      const float* __restrict__ fc_b) {
    int t = threadIdx.x;
    if (blockIdx.x < 144) {
        int f = blockIdx.x*256 + t;            // 36864 elements
        int e    = f & 31;
        int lane = (f >> 5) & 31;
        int n0i  = (f >> 10) & 3;
        int slab = f >> 12;
        int j = e >> 4, r = e & 15;
        int s = r >> 2, pair = (r >> 1) & 1, within = r & 1;
        int g = lane >> 2, tq = lane & 3;
        int o  = n0i*16 + j*8 + g;
        int ch = 2*tq + 16*s + 8*pair + within;
        g_wtf[f] = __float2half_rn(w[o*576 + ch*9 + slab]);
    } else {
        __shared__ float r_s[4];
        if (t < 128) {                          // warp per fc row, lane per 2 channels
            int t4 = t >> 5, l = t & 31;
            const float inv = 1.f / (float)HWP;
            float p0 = g_pooled[2*l]   * inv;   // already summed over both batches? no:
            // g_pooled[b*64+c]; need (b0 + b1) per channel
            p0 = (g_pooled[2*l]   + g_pooled[64 + 2*l])   * inv;
            float p1 = (g_pooled[2*l+1] + g_pooled[64 + 2*l+1]) * inv;
            float s = p0 * fc_w[t4*64 + 2*l] + p1 * fc_w[t4*64 + 2*l+1];
            #pragma unroll
            for (int o = 16; o > 0; o >>= 1) s += __shfl_down_sync(0xffffffffu, s, o);
            if (l == 0) r_s[t4] = 1.f / (1.f + expf(-(s + fc_b[t4])));
        }
        __syncthreads();
        // re-zero pooled accumulator for the next graph replay (after consumption)
        if (t < 128) g_pooled[t] = 0.f;
        for (int e = t; e < 648; e += 256) {
            int g = e / 81, kk = e % 81;
            int k = kk / 9, k2 = kk % 9;
            int pk = c_P2[g][k];
            float mb = c_Mbase[pk*9 + k2];
            float v;
            if ((g & 1) == 0) {
                float rr = r_s[g >> 1];
                v = rr * mb + (1.f - rr) * ((k2 == pk) ? 1.f : 0.f);
            } else {
                v = mb;
            }
            g_Mg[e] = v;
        }
    }
}

// ---------------- kernel 4: fused DCN (sample + transform + fp16 MMA GEMM) ----------------
// smem layout (float units), total 16008 floats = 64032 B:
//   U half[32 px][584]   @ 0      (9344 floats)  row = 9 slabs x 64 halves + 8 pad halves
//   A_s [32][9][12]      @ 9344   (3584)   (phase0/1) -- aliased by outb[64][33] in epilogue
//   idx_s[32*9][4] int   @ 12928  (1152)
//   wgt_s[32*9][4x half2]@ 14080  (1152)
//   wc8T[8][33]          @ 15232  (264)
//   bias_s[512]          @ 15496  (512)
#define USTRH    584
#define A_OFF    9344
#define IDX_OFF  12928
#define WGT_OFF  14080
#define OUTB_OFF 9344
#define WC8_OFF  15232
#define BIAS_OFF 15496
#define SMEM_FLOATS 16008
#define SMEM_BYTES  (SMEM_FLOATS*4)

__global__ __launch_bounds__(256, 3) void main_kernel(
    const float* __restrict__ offset, const float* __restrict__ mask,
    const float* __restrict__ wc8g,   const float* __restrict__ bias,
    float* __restrict__ out)
{
    extern __shared__ float sm[];
    __half* u_h  = (__half*)sm;
    float* A_s   = sm + A_OFF;
    int*   idx_s = (int*)(sm + IDX_OFF);
    __half2* wgt_h = (__half2*)(sm + WGT_OFF);
    float* outb  = sm + OUTB_OFF;
    float* wc8T  = sm + WC8_OFF;
    float* bias_s= sm + BIAS_OFF;

    int t     = threadIdx.x;
    int bid   = blockIdx.x;               // 1024: b(2) * 512 tiles
    int b     = bid >> 9;
    int tbase = (bid & 511) << 5;
    int h     = tbase >> 7;
    int w0    = tbase & 127;
    int w     = t >> 5;
    int l     = t & 31;

    // ---- phase 0a: wc8 (transposed), bias staging ----
    wc8T[w*33 + l] = wc8g[((b*8 + w) << 14) + tbase + l];
    bias_s[t]       = bias[t];
    bias_s[t + 256] = bias[t + 256];

    // ---- phase 0b: bilinear indices & packed fp16 weights (mask folded) ----
    for (int task = t; task < 288; task += 256) {
        int p = task & 31, k = task >> 5;
        int pix = tbase + p;
        float offy = offset[((b*18 + 2*k    ) << 14) + pix];
        float offx = offset[((b*18 + 2*k + 1) << 14) + pix];
        float mval = mask  [((b*9  + k      ) << 14) + pix];
        float py = (float)h        + (float)(k/3) - 1.f + offy;
        float px = (float)(w0 + p) + (float)(k%3) - 1.f + offx;
        float y0f = floorf(py), x0f = floorf(px);
        float ly = py - y0f, lx = px - x0f;
        int y0 = (int)y0f, x0i = (int)x0f;
        int y1 = y0 + 1, x1 = x0i + 1;
        bool vy0 = (y0 >= 0) & (y0 <= 127);
        bool vy1 = (y1 >= 0) & (y1 <= 127);
        bool vx0 = (x0i >= 0) & (x0i <= 127);
        bool vx1 = (x1 >= 0) & (x1 <= 127);
        float w00 = (1.f-ly)*(1.f-lx) * ((vy0 & vx0) ? mval : 0.f);
        float w01 = (1.f-ly)*lx       * ((vy0 & vx1) ? mval : 0.f);
        float w10 = ly*(1.f-lx)       * ((vy1 & vx0) ? mval : 0.f);
        float w11 = ly*lx             * ((vy1 & vx1) ? mval : 0.f);
        int cy0 = min(max(y0, 0), 127), cy1 = min(max(y1, 0), 127);
        int cx0 = min(max(x0i,0), 127), cx1 = min(max(x1, 0), 127);
        int b4 = (p*9 + k)*4;
        idx_s[b4+0] = cy0*128 + cx0;
        idx_s[b4+1] = cy0*128 + cx1;
        idx_s[b4+2] = cy1*128 + cx0;
        idx_s[b4+3] = cy1*128 + cx1;
        wgt_h[b4+0] = __floats2half2_rn(w00, w00);
        wgt_h[b4+1] = __floats2half2_rn(w01, w01);
        wgt_h[b4+2] = __floats2half2_rn(w10, w10);
        wgt_h[b4+3] = __floats2half2_rn(w11, w11);
    }
    __syncthreads();

    // ---- phase 0c: A[p][k][k2] = sum_g wc8[g] * M_g ----
    for (int e = t; e < 2592; e += 256) {
        int p = e & 31, kk = e >> 5;
        int k = kk / 9, k2 = kk - k*9;
        float a = 0.f;
        #pragma unroll
        for (int g = 0; g < 8; g++) a += wc8T[g*33 + p] * g_Mg[g*81 + kk];
        A_s[p*112 + k*12 + k2] = a;
    }
    __syncthreads();

    // ---- phase 1: fp16 gather + HFMA2 bilinear + fp32 tap transform -> u_h ----
    {
        const __half2* ib = (const __half2*)g_nhwc_h + ((size_t)b << 19);  // b * 16384 * 32 half2
        const int4* idx4 = (const int4*)idx_s;
        const uint4* wgt4 = (const uint4*)wgt_h;
        // pos of channel 2l within a slab's 64 halves (within=0; 2l+1 is pos+1)
        int pos = (l & 3)*16 + (l >> 3)*4 + ((l >> 2) & 1)*2;
        #pragma unroll
        for (int pp = 0; pp < 4; pp++) {
            int p = w*4 + pp;
            float2 ua[9];
            #pragma unroll
            for (int i = 0; i < 9; i++) { ua[i].x = 0.f; ua[i].y = 0.f; }
            #pragma unroll
            for (int k = 0; k < 9; k++) {
                int4  id = idx4[p*9 + k];
                uint4 wq = wgt4[p*9 + k];
                __half2 w00 = *(__half2*)&wq.x;
                __half2 w01 = *(__half2*)&wq.y;
                __half2 w10 = *(__half2*)&wq.z;
                __half2 w11 = *(__half2*)&wq.w;
                __half2 vh = __hmul2(ib[id.x*32 + l], w00);
                vh = __hfma2(ib[id.y*32 + l], w01, vh);
                vh = __hfma2(ib[id.z*32 + l], w10, vh);
                vh = __hfma2(ib[id.w*32 + l], w11, vh);
                float vx = __low2float(vh);
                float vy = __high2float(vh);
                const float* Ab = A_s + p*112 + k*12;
                float4 a0 = *(const float4*)(Ab);
                float4 a1 = *(const float4*)(Ab + 4);
                float  a8 = Ab[8];
                ua[0].x += a0.x*vx; ua[0].y += a0.x*vy;
                ua[1].x += a0.y*vx; ua[1].y += a0.y*vy;
                ua[2].x += a0.z*vx; ua[2].y += a0.z*vy;
                ua[3].x += a0.w*vx; ua[3].y += a0.w*vy;
                ua[4].x += a1.x*vx; ua[4].y += a1.x*vy;
                ua[5].x += a1.y*vx; ua[5].y += a1.y*vy;
                ua[6].x += a1.z*vx; ua[6].y += a1.z*vy;
                ua[7].x += a1.w*vx; ua[7].y += a1.w*vy;
                ua[8].x += a8  *vx; ua[8].y += a8  *vy;
            }
            __half* urow = u_h + p*USTRH;
            #pragma unroll
            for (int k2 = 0; k2 < 9; k2++) {
                *(__half2*)(urow + k2*64 + pos) = __floats2half2_rn(ua[k2].x, ua[k2].y);
            }
        }
    }
    __syncthreads();

    // ---- phase 2: fp16 MMA  D[32px x 64o] = u[32 x 576] * W[576 x 64]  (no barriers) ----
    int m0  = (w & 1) * 16;
    int n0i = w >> 1;
    int g   = l >> 2;
    int tq  = l & 3;
    const __half* uR0 = u_h + (m0 + g)*USTRH + tq*16;
    const __half* uR1 = uR0 + 8*USTRH;
    const __half* Bb  = g_wtf + (n0i*32 + l)*32;

    float acc[2][4];
    #pragma unroll
    for (int j = 0; j < 2; j++)
        #pragma unroll
        for (int i = 0; i < 4; i++) acc[j][i] = 0.f;

    #pragma unroll
    for (int ch = 0; ch < 9; ch++) {
        uint32_t Ag0[8], Ag1[8], Bw[16];
        *(uint4*)(Ag0)     = *(const uint4*)(uR0 + ch*64);
        *(uint4*)(Ag0 + 4) = *(const uint4*)(uR0 + ch*64 + 8);
        *(uint4*)(Ag1)     = *(const uint4*)(uR1 + ch*64);
        *(uint4*)(Ag1 + 4) = *(const uint4*)(uR1 + ch*64 + 8);
        const uint4* Bp = (const uint4*)(Bb + ch*4096);
        *(uint4*)(Bw)      = Bp[0];
        *(uint4*)(Bw + 4)  = Bp[1];
        *(uint4*)(Bw + 8)  = Bp[2];
        *(uint4*)(Bw + 12) = Bp[3];
        #pragma unroll
        for (int s = 0; s < 4; s++) {
            uint32_t a0 = Ag0[s*2], a2 = Ag0[s*2+1];
            uint32_t a1 = Ag1[s*2], a3 = Ag1[s*2+1];
            #pragma unroll
            for (int j = 0; j < 2; j++) {
                uint32_t b0 = Bw[j*8 + s*2], b1 = Bw[j*8 + s*2 + 1];
                asm volatile(
                    "mma.sync.aligned.m16n8k16.row.col.f32.f16.f16.f32 "
                    "{%0,%1,%2,%3}, {%4,%5,%6,%7}, {%8,%9}, {%0,%1,%2,%3};\n"
                    : "+f"(acc[j][0]), "+f"(acc[j][1]), "+f"(acc[j][2]), "+f"(acc[j][3])
                    : "r"(a0), "r"(a1), "r"(a2), "r"(a3), "r"(b0), "r"(b1));
            }
        }
    }

    // ---- epilogue: stage D in smem (outb[o][px]), coalesced NCHW store + bias ----
    __syncthreads();
    #pragma unroll
    for (int j = 0; j < 2; j++) {
        int o = n0i*16 + j*8 + 2*tq;
        outb[(o    )*33 + m0 + g    ] = acc[j][0];
        outb[(o + 1)*33 + m0 + g    ] = acc[j][1];
        outb[(o    )*33 + m0 + g + 8] = acc[j][2];
        outb[(o + 1)*33 + m0 + g + 8] = acc[j][3];
    }
    __syncthreads();
    #pragma unroll
    for (int r = 0; r < 8; r++) {
        int o = r*8 + w;       // constant per warp
        int p = l;
        float be = 0.f;
        #pragma unroll
        for (int gg = 0; gg < 8; gg++) be += wc8T[gg*33 + p] * bias_s[gg*64 + o];
        out[((b*64 + o) << 14) + tbase + p] = outb[o*33 + p] + be;
    }
}

// ---------------- launch ----------------
extern "C" void kernel_launch(void* const* d_in, const int* in_sizes, int n_in,
                              void* d_out, int out_size) {
    const float* input  = (const float*)d_in[0];
    const float* offset = (const float*)d_in[1];
    const float* maskp  = (const float*)d_in[2];
    const float* w_c8   = (const float*)d_in[3];
    const float* weight = (const float*)d_in[4];
    const float* bias   = (const float*)d_in[5];
    const float* fc_w   = (const float*)d_in[6];
    const float* fc_b   = (const float*)d_in[7];
    float* out = (float*)d_out;

    cudaFuncSetAttribute(main_kernel, cudaFuncAttributeMaxDynamicSharedMemorySize, SMEM_BYTES);

    nhwc_kernel   <<<1024, 256>>>(input);
    wtsetup_kernel<<<145, 256>>>(weight, fc_w, fc_b);
    main_kernel   <<<1024, 256, SMEM_BYTES>>>(offset, maskp, w_c8, bias, out);
}

// round 12
// speedup vs baseline: 1.9554x; 1.2376x over previous
#include <cuda_runtime.h>
#include <cuda_fp16.h>
#include <cstdint>
#include <math.h>

#define HH 128
#define WWD 128
#define HWP (HH*WWD)
#define BB 2

// ---------------- device scratch ----------------
__device__ __half g_nhwc_h[BB*HWP*64]; // 4 MB, input in NHWC (fp16)
__device__ float g_pooled[BB*64];      // per (b,c) plane sums (atomic; zero-init, re-zeroed each call)
__device__ float g_Mg[8*81];           // 8 tap-transform matrices (9x9)
__device__ __half g_wtf[9*4*4*32*8];   // W fragment stream [slab][n0i][chunk][lane][8 halves]

#define SMV 0.20710678118654746f
#define M2V 0.08578643762690495f
__device__ const float c_Mbase[81] = {
    0.5f, SMV , 0.f , SMV , M2V , 0.f , 0.f , 0.f , 0.f ,
    0.f , 1.f , 0.f , 0.f , 0.f , 0.f , 0.f , 0.f , 0.f ,
    0.f , SMV , 0.5f, 0.f , M2V , SMV , 0.f , 0.f , 0.f ,
    0.f , 0.f , 0.f , 1.f , 0.f , 0.f , 0.f , 0.f , 0.f ,
    0.f , 0.f , 0.f , 0.f , 1.f , 0.f , 0.f , 0.f , 0.f ,
    0.f , 0.f , 0.f , 0.f , 0.f , 1.f , 0.f , 0.f , 0.f ,
    0.f , 0.f , 0.f , SMV , M2V , 0.f , 0.5f, SMV , 0.f ,
    0.f , 0.f , 0.f , 0.f , 0.f , 0.f , 0.f , 1.f , 0.f ,
    0.f , 0.f , 0.f , 0.f , M2V , SMV , 0.f , SMV , 0.5f
};

__device__ const int c_P2[8][9] = {
    {0,1,2,3,4,5,6,7,8},
    {3,0,1,6,4,2,7,8,5},
    {6,3,0,7,4,1,8,5,2},
    {7,6,3,8,4,0,5,2,1},
    {8,7,6,5,4,3,2,1,0},
    {5,8,7,2,4,6,1,0,3},
    {2,5,8,1,4,7,0,3,6},
    {1,2,5,0,4,8,3,6,7}
};

// ---------------- kernel 1: NCHW -> NHWC transpose (fp32 -> fp16) + pooled sums ----------------
__global__ __launch_bounds__(256) void nhwc_kernel(const float* __restrict__ in) {
    __shared__ float tile[64][33];
    int bid = blockIdx.x;
    int b   = bid >> 9;
    int rem = bid & 511;
    int y   = rem >> 2;
    int x0  = (rem & 3) << 5;
    int t   = threadIdx.x;

    int xl = t & 31, cb = t >> 5;
    #pragma unroll
    for (int i = 0; i < 8; i++) {
        int c = cb + i*8;
        tile[c][xl] = in[(((b*64 + c)*128 + y)*128) + x0 + xl];
    }
    __syncthreads();
    int c2 = t & 63, xb = t >> 6;
    #pragma unroll
    for (int i = 0; i < 8; i++) {
        int x = xb + i*4;
        g_nhwc_h[(((b*128 + y)*128) + x0 + x)*64 + c2] = __float2half_rn(tile[c2][x]);
    }
    // pooled channel sums for this (b, y, x-chunk): accumulate atomically
    if (t < 64) {
        float s = 0.f;
        #pragma unroll
        for (int x = 0; x < 32; x++) s += tile[t][x];
        atomicAdd(&g_pooled[b*64 + t], s);
    }
}

// ---------------- kernel 3: W fragment stream (blocks 0..143) + setup (block 144) ----------------
// g_wtf flat index f = slab*4096 + n0i*1024 + q*256 + lane*8 + r   (coalesced per chunk q)
//   e = q*8 + r  (e in 0..31: the lane's fragment-half index)
//   e = j*16 + s*4 + pair*2 + within
//   o  = n0i*16 + j*8 + (lane>>2)
//   ch = 2*(lane&3) + 16*s + 8*pair + within      (ch = within-slab channel c)
//   value = weight[o][c=ch][k2=slab]  (weight layout o*576 + c*9 + k2)
__global__ __launch_bounds__(256) void wtsetup_kernel(const float* __restrict__ w,
                                                      const float* __restrict__ fc_w,
                                                      const float* __restrict__ fc_b) {
    int t = threadIdx.x;
    if (blockIdx.x < 144) {
        int f = blockIdx.x*256 + t;            // 36864 elements
        int r    = f & 7;
        int lane = (f >> 3) & 31;
        int q    = (f >> 8) & 3;
        int n0i  = (f >> 10) & 3;
        int slab = f >> 12;
        int e = q*8 + r;
        int j = e >> 4, rr = e & 15;
        int s = rr >> 2, pair = (rr >> 1) & 1, within = rr & 1;
        int g = lane >> 2, tq = lane & 3;
        int o  = n0i*16 + j*8 + g;
        int ch = 2*tq + 16*s + 8*pair + within;
        g_wtf[f] = __float2half_rn(w[o*576 + ch*9 + slab]);
    } else {
        __shared__ float r_s[4];
        if (t < 128) {                          // warp per fc row, lane per 2 channels
            int t4 = t >> 5, l = t & 31;
            const float inv = 1.f / (float)HWP;
            float p0 = (g_pooled[2*l]   + g_pooled[64 + 2*l])   * inv;
            float p1 = (g_pooled[2*l+1] + g_pooled[64 + 2*l+1]) * inv;
            float s = p0 * fc_w[t4*64 + 2*l] + p1 * fc_w[t4*64 + 2*l+1];
            #pragma unroll
            for (int o = 16; o > 0; o >>= 1) s += __shfl_down_sync(0xffffffffu, s, o);
            if (l == 0) r_s[t4] = 1.f / (1.f + expf(-(s + fc_b[t4])));
        }
        __syncthreads();
        // re-zero pooled accumulator for the next graph replay (after consumption)
        if (t < 128) g_pooled[t] = 0.f;
        for (int e = t; e < 648; e += 256) {
            int g = e / 81, kk = e % 81;
            int k = kk / 9, k2 = kk % 9;
            int pk = c_P2[g][k];
            float mb = c_Mbase[pk*9 + k2];
            float v;
            if ((g & 1) == 0) {
                float rr = r_s[g >> 1];
                v = rr * mb + (1.f - rr) * ((k2 == pk) ? 1.f : 0.f);
            } else {
                v = mb;
            }
            g_Mg[e] = v;
        }
    }
}

// ---------------- kernel 4: fused DCN (sample + transform + fp16 MMA GEMM) ----------------
// smem layout (float units), total 16008 floats = 64032 B:
//   U half[32 px][584]   @ 0      (9344 floats)  row = 9 slabs x 64 halves + 8 pad halves
//   A_s [32][9][12]      @ 9344   (3584)   (phase0/1) -- aliased by outb[64][33] in epilogue
//   idx_s[32*9][4] int   @ 12928  (1152)
//   wgt_s[32*9][4x half2]@ 14080  (1152)
//   wc8T[8][33]          @ 15232  (264)
//   bias_s[512]          @ 15496  (512)
#define USTRH    584
#define A_OFF    9344
#define IDX_OFF  12928
#define WGT_OFF  14080
#define OUTB_OFF 9344
#define WC8_OFF  15232
#define BIAS_OFF 15496
#define SMEM_FLOATS 16008
#define SMEM_BYTES  (SMEM_FLOATS*4)

__global__ __launch_bounds__(256, 3) void main_kernel(
    const float* __restrict__ offset, const float* __restrict__ mask,
    const float* __restrict__ wc8g,   const float* __restrict__ bias,
    float* __restrict__ out)
{
    extern __shared__ float sm[];
    __half* u_h  = (__half*)sm;
    float* A_s   = sm + A_OFF;
    int*   idx_s = (int*)(sm + IDX_OFF);
    __half2* wgt_h = (__half2*)(sm + WGT_OFF);
    float* outb  = sm + OUTB_OFF;
    float* wc8T  = sm + WC8_OFF;
    float* bias_s= sm + BIAS_OFF;

    int t     = threadIdx.x;
    int bid   = blockIdx.x;               // 1024: b(2) * 512 tiles
    int b     = bid >> 9;
    int tbase = (bid & 511) << 5;
    int h     = tbase >> 7;
    int w0    = tbase & 127;
    int w     = t >> 5;
    int l     = t & 31;

    // ---- phase 0a: wc8 (transposed), bias staging ----
    wc8T[w*33 + l] = wc8g[((b*8 + w) << 14) + tbase + l];
    bias_s[t]       = bias[t];
    bias_s[t + 256] = bias[t + 256];

    // ---- phase 0b: bilinear indices & packed fp16 weights (mask folded) ----
    for (int task = t; task < 288; task += 256) {
        int p = task & 31, k = task >> 5;
        int pix = tbase + p;
        float offy = offset[((b*18 + 2*k    ) << 14) + pix];
        float offx = offset[((b*18 + 2*k + 1) << 14) + pix];
        float mval = mask  [((b*9  + k      ) << 14) + pix];
        float py = (float)h        + (float)(k/3) - 1.f + offy;
        float px = (float)(w0 + p) + (float)(k%3) - 1.f + offx;
        float y0f = floorf(py), x0f = floorf(px);
        float ly = py - y0f, lx = px - x0f;
        int y0 = (int)y0f, x0i = (int)x0f;
        int y1 = y0 + 1, x1 = x0i + 1;
        bool vy0 = (y0 >= 0) & (y0 <= 127);
        bool vy1 = (y1 >= 0) & (y1 <= 127);
        bool vx0 = (x0i >= 0) & (x0i <= 127);
        bool vx1 = (x1 >= 0) & (x1 <= 127);
        float w00 = (1.f-ly)*(1.f-lx) * ((vy0 & vx0) ? mval : 0.f);
        float w01 = (1.f-ly)*lx       * ((vy0 & vx1) ? mval : 0.f);
        float w10 = ly*(1.f-lx)       * ((vy1 & vx0) ? mval : 0.f);
        float w11 = ly*lx             * ((vy1 & vx1) ? mval : 0.f);
        int cy0 = min(max(y0, 0), 127), cy1 = min(max(y1, 0), 127);
        int cx0 = min(max(x0i,0), 127), cx1 = min(max(x1, 0), 127);
        int b4 = (p*9 + k)*4;
        idx_s[b4+0] = cy0*128 + cx0;
        idx_s[b4+1] = cy0*128 + cx1;
        idx_s[b4+2] = cy1*128 + cx0;
        idx_s[b4+3] = cy1*128 + cx1;
        wgt_h[b4+0] = __floats2half2_rn(w00, w00);
        wgt_h[b4+1] = __floats2half2_rn(w01, w01);
        wgt_h[b4+2] = __floats2half2_rn(w10, w10);
        wgt_h[b4+3] = __floats2half2_rn(w11, w11);
    }
    __syncthreads();

    // ---- phase 0c: A[p][k][k2] = sum_g wc8[g] * M_g ----
    for (int e = t; e < 2592; e += 256) {
        int p = e & 31, kk = e >> 5;
        int k = kk / 9, k2 = kk - k*9;
        float a = 0.f;
        #pragma unroll
        for (int g = 0; g < 8; g++) a += wc8T[g*33 + p] * g_Mg[g*81 + kk];
        A_s[p*112 + k*12 + k2] = a;
    }
    __syncthreads();

    // ---- phase 1: fp16 gather + HFMA2 bilinear + fp32 tap transform -> u_h ----
    {
        const __half2* ib = (const __half2*)g_nhwc_h + ((size_t)b << 19);  // b * 16384 * 32 half2
        const int4* idx4 = (const int4*)idx_s;
        const uint4* wgt4 = (const uint4*)wgt_h;
        // pos of channel 2l within a slab's 64 halves (within=0; 2l+1 is pos+1)
        int pos = (l & 3)*16 + (l >> 3)*4 + ((l >> 2) & 1)*2;
        #pragma unroll
        for (int pp = 0; pp < 4; pp++) {
            int p = w*4 + pp;
            float2 ua[9];
            #pragma unroll
            for (int i = 0; i < 9; i++) { ua[i].x = 0.f; ua[i].y = 0.f; }
            #pragma unroll
            for (int k = 0; k < 9; k++) {
                int4  id = idx4[p*9 + k];
                uint4 wq = wgt4[p*9 + k];
                __half2 w00 = *(__half2*)&wq.x;
                __half2 w01 = *(__half2*)&wq.y;
                __half2 w10 = *(__half2*)&wq.z;
                __half2 w11 = *(__half2*)&wq.w;
                __half2 vh = __hmul2(ib[id.x*32 + l], w00);
                vh = __hfma2(ib[id.y*32 + l], w01, vh);
                vh = __hfma2(ib[id.z*32 + l], w10, vh);
                vh = __hfma2(ib[id.w*32 + l], w11, vh);
                float vx = __low2float(vh);
                float vy = __high2float(vh);
                const float* Ab = A_s + p*112 + k*12;
                float4 a0 = *(const float4*)(Ab);
                float4 a1 = *(const float4*)(Ab + 4);
                float  a8 = Ab[8];
                ua[0].x += a0.x*vx; ua[0].y += a0.x*vy;
                ua[1].x += a0.y*vx; ua[1].y += a0.y*vy;
                ua[2].x += a0.z*vx; ua[2].y += a0.z*vy;
                ua[3].x += a0.w*vx; ua[3].y += a0.w*vy;
                ua[4].x += a1.x*vx; ua[4].y += a1.x*vy;
                ua[5].x += a1.y*vx; ua[5].y += a1.y*vy;
                ua[6].x += a1.z*vx; ua[6].y += a1.z*vy;
                ua[7].x += a1.w*vx; ua[7].y += a1.w*vy;
                ua[8].x += a8  *vx; ua[8].y += a8  *vy;
            }
            __half* urow = u_h + p*USTRH;
            #pragma unroll
            for (int k2 = 0; k2 < 9; k2++) {
                *(__half2*)(urow + k2*64 + pos) = __floats2half2_rn(ua[k2].x, ua[k2].y);
            }
        }
    }
    __syncthreads();

    // ---- phase 2: fp16 MMA  D[32px x 64o] = u[32 x 576] * W[576 x 64]  (no barriers) ----
    int m0  = (w & 1) * 16;
    int n0i = w >> 1;
    int g   = l >> 2;
    int tq  = l & 3;
    const __half* uR0 = u_h + (m0 + g)*USTRH + tq*16;
    const __half* uR1 = uR0 + 8*USTRH;
    const __half* Bb  = g_wtf + n0i*1024 + l*8;   // [slab][n0i][q][lane][8h]

    float acc[2][4];
    #pragma unroll
    for (int j = 0; j < 2; j++)
        #pragma unroll
        for (int i = 0; i < 4; i++) acc[j][i] = 0.f;

    #pragma unroll
    for (int ch = 0; ch < 9; ch++) {
        uint32_t Ag0[8], Ag1[8], Bw[16];
        *(uint4*)(Ag0)     = *(const uint4*)(uR0 + ch*64);
        *(uint4*)(Ag0 + 4) = *(const uint4*)(uR0 + ch*64 + 8);
        *(uint4*)(Ag1)     = *(const uint4*)(uR1 + ch*64);
        *(uint4*)(Ag1 + 4) = *(const uint4*)(uR1 + ch*64 + 8);
        const __half* Bc = Bb + ch*4096;
        *(uint4*)(Bw)      = *(const uint4*)(Bc);         // chunk 0: lane-contiguous 512B
        *(uint4*)(Bw + 4)  = *(const uint4*)(Bc + 256);   // chunk 1
        *(uint4*)(Bw + 8)  = *(const uint4*)(Bc + 512);   // chunk 2
        *(uint4*)(Bw + 12) = *(const uint4*)(Bc + 768);   // chunk 3
        #pragma unroll
        for (int s = 0; s < 4; s++) {
            uint32_t a0 = Ag0[s*2], a2 = Ag0[s*2+1];
            uint32_t a1 = Ag1[s*2], a3 = Ag1[s*2+1];
            #pragma unroll
            for (int j = 0; j < 2; j++) {
                uint32_t b0 = Bw[j*8 + s*2], b1 = Bw[j*8 + s*2 + 1];
                asm volatile(
                    "mma.sync.aligned.m16n8k16.row.col.f32.f16.f16.f32 "
                    "{%0,%1,%2,%3}, {%4,%5,%6,%7}, {%8,%9}, {%0,%1,%2,%3};\n"
                    : "+f"(acc[j][0]), "+f"(acc[j][1]), "+f"(acc[j][2]), "+f"(acc[j][3])
                    : "r"(a0), "r"(a1), "r"(a2), "r"(a3), "r"(b0), "r"(b1));
            }
        }
    }

    // ---- epilogue: stage D in smem (outb[o][px]), coalesced NCHW store + bias ----
    __syncthreads();
    #pragma unroll
    for (int j = 0; j < 2; j++) {
        int o = n0i*16 + j*8 + 2*tq;
        outb[(o    )*33 + m0 + g    ] = acc[j][0];
        outb[(o + 1)*33 + m0 + g    ] = acc[j][1];
        outb[(o    )*33 + m0 + g + 8] = acc[j][2];
        outb[(o + 1)*33 + m0 + g + 8] = acc[j][3];
    }
    __syncthreads();
    #pragma unroll
    for (int r = 0; r < 8; r++) {
        int o = r*8 + w;       // constant per warp
        int p = l;
        float be = 0.f;
        #pragma unroll
        for (int gg = 0; gg < 8; gg++) be += wc8T[gg*33 + p] * bias_s[gg*64 + o];
        out[((b*64 + o) << 14) + tbase + p] = outb[o*33 + p] + be;
    }
}

// ---------------- launch ----------------
extern "C" void kernel_launch(void* const* d_in, const int* in_sizes, int n_in,
                              void* d_out, int out_size) {
    const float* input  = (const float*)d_in[0];
    const float* offset = (const float*)d_in[1];
    const float* maskp  = (const float*)d_in[2];
    const float* w_c8   = (const float*)d_in[3];
    const float* weight = (const float*)d_in[4];
    const float* bias   = (const float*)d_in[5];
    const float* fc_w   = (const float*)d_in[6];
    const float* fc_b   = (const float*)d_in[7];
    float* out = (float*)d_out;

    cudaFuncSetAttribute(main_kernel, cudaFuncAttributeMaxDynamicSharedMemorySize, SMEM_BYTES);

    nhwc_kernel   <<<1024, 256>>>(input);
    wtsetup_kernel<<<145, 256>>>(weight, fc_w, fc_b);
    main_kernel   <<<1024, 256, SMEM_BYTES>>>(offset, maskp, w_c8, bias, out);
}

// round 13
// speedup vs baseline: 2.0269x; 1.0366x over previous
#include <cuda_runtime.h>
#include <cuda_fp16.h>
#include <cstdint>
#include <math.h>

#define HH 128
#define WWD 128
#define HWP (HH*WWD)
#define BB 2

// ---------------- device scratch ----------------
__device__ __half g_nhwc_h[BB*HWP*64]; // 4 MB, input in NHWC (fp16)
__device__ float g_pooled[BB*64];      // per (b,c) plane sums (atomic; zero-init, re-zeroed each call)
__device__ float g_Mg[8*81];           // 8 tap-transform matrices (9x9)
__device__ __half g_wtf[9*4*4*32*8];   // W fragment stream [slab][n0i][chunk][lane][8 halves]

#define SMV 0.20710678118654746f
#define M2V 0.08578643762690495f
__device__ const float c_Mbase[81] = {
    0.5f, SMV , 0.f , SMV , M2V , 0.f , 0.f , 0.f , 0.f ,
    0.f , 1.f , 0.f , 0.f , 0.f , 0.f , 0.f , 0.f , 0.f ,
    0.f , SMV , 0.5f, 0.f , M2V , SMV , 0.f , 0.f , 0.f ,
    0.f , 0.f , 0.f , 1.f , 0.f , 0.f , 0.f , 0.f , 0.f ,
    0.f , 0.f , 0.f , 0.f , 1.f , 0.f , 0.f , 0.f , 0.f ,
    0.f , 0.f , 0.f , 0.f , 0.f , 1.f , 0.f , 0.f , 0.f ,
    0.f , 0.f , 0.f , SMV , M2V , 0.f , 0.5f, SMV , 0.f ,
    0.f , 0.f , 0.f , 0.f , 0.f , 0.f , 0.f , 1.f , 0.f ,
    0.f , 0.f , 0.f , 0.f , M2V , SMV , 0.f , SMV , 0.5f
};

__device__ const int c_P2[8][9] = {
    {0,1,2,3,4,5,6,7,8},
    {3,0,1,6,4,2,7,8,5},
    {6,3,0,7,4,1,8,5,2},
    {7,6,3,8,4,0,5,2,1},
    {8,7,6,5,4,3,2,1,0},
    {5,8,7,2,4,6,1,0,3},
    {2,5,8,1,4,7,0,3,6},
    {1,2,5,0,4,8,3,6,7}
};

// ---------------- kernel 1: NCHW->NHWC fp16 transpose + pooled sums (blocks 0..1023)
//                  + W fragment stream build (blocks 1024..1167) ----------------
__global__ __launch_bounds__(256) void nhwc_kernel(const float* __restrict__ in,
                                                   const float* __restrict__ wgt) {
    int bid = blockIdx.x;
    int t   = threadIdx.x;
    if (bid < 1024) {
        __shared__ float tile[64][33];
        int b   = bid >> 9;
        int rem = bid & 511;
        int y   = rem >> 2;
        int x0  = (rem & 3) << 5;

        int xl = t & 31, cb = t >> 5;
        #pragma unroll
        for (int i = 0; i < 8; i++) {
            int c = cb + i*8;
            tile[c][xl] = in[(((b*64 + c)*128 + y)*128) + x0 + xl];
        }
        __syncthreads();
        int cp = t & 31;          // channel pair: c = 2cp, 2cp+1
        int xs = t >> 5;          // 0..7
        #pragma unroll
        for (int i = 0; i < 4; i++) {
            int x = xs + i*8;
            __half2 v = __floats2half2_rn(tile[2*cp][x], tile[2*cp+1][x]);
            *(__half2*)&g_nhwc_h[(((b*128 + y)*128) + x0 + x)*64 + 2*cp] = v;
        }
        if (t < 64) {
            float s = 0.f;
            #pragma unroll
            for (int x = 0; x < 32; x++) s += tile[t][x];
            atomicAdd(&g_pooled[b*64 + t], s);
        }
    } else {
        // W fragment stream: f = slab*4096 + n0i*1024 + q*256 + lane*8 + r
        int f = (bid - 1024)*256 + t;          // 36864 elements
        int r    = f & 7;
        int lane = (f >> 3) & 31;
        int q    = (f >> 8) & 3;
        int n0i  = (f >> 10) & 3;
        int slab = f >> 12;
        int e = q*8 + r;
        int j = e >> 4, rr = e & 15;
        int s = rr >> 2, pair = (rr >> 1) & 1, within = rr & 1;
        int g = lane >> 2, tq = lane & 3;
        int o  = n0i*16 + j*8 + g;
        int ch = 2*tq + 16*s + 8*pair + within;
        g_wtf[f] = __float2half_rn(wgt[o*576 + ch*9 + slab]);
    }
}

// ---------------- kernel 2: setup — r = sigmoid(fc), build M_g, re-zero pooled ----------------
__global__ __launch_bounds__(256) void setup_kernel(const float* __restrict__ fc_w,
                                                    const float* __restrict__ fc_b) {
    int t = threadIdx.x;
    __shared__ float r_s[4];
    if (t < 128) {                          // warp per fc row, lane per 2 channels
        int t4 = t >> 5, l = t & 31;
        const float inv = 1.f / (float)HWP;
        float p0 = (g_pooled[2*l]   + g_pooled[64 + 2*l])   * inv;
        float p1 = (g_pooled[2*l+1] + g_pooled[64 + 2*l+1]) * inv;
        float s = p0 * fc_w[t4*64 + 2*l] + p1 * fc_w[t4*64 + 2*l+1];
        #pragma unroll
        for (int o = 16; o > 0; o >>= 1) s += __shfl_down_sync(0xffffffffu, s, o);
        if (l == 0) r_s[t4] = 1.f / (1.f + expf(-(s + fc_b[t4])));
    }
    __syncthreads();
    if (t < 128) g_pooled[t] = 0.f;   // re-zero for next graph replay
    for (int e = t; e < 648; e += 256) {
        int g = e / 81, kk = e % 81;
        int k = kk / 9, k2 = kk % 9;
        int pk = c_P2[g][k];
        float mb = c_Mbase[pk*9 + k2];
        float v;
        if ((g & 1) == 0) {
            float rr = r_s[g >> 1];
            v = rr * mb + (1.f - rr) * ((k2 == pk) ? 1.f : 0.f);
        } else {
            v = mb;
        }
        g_Mg[e] = v;
    }
}

// ---------------- kernel 4: fused DCN (sample + transform + fp16 MMA GEMM) ----------------
// smem layout (float units), total 16136 floats = 64544 B:
//   U half[32 px][584]   @ 0      (9344 floats)
//   A_s [32][116]        @ 9344   (3712)  stride 116 (20 mod 32 -> 4-way max on stores)
//                                  -- aliased by outb[64][33] (2112) in epilogue
//   idx_s[32*9][4] int   @ 13056  (1152)
//   wgt_s[32*9][4 half2] @ 14208  (1152)
//   wc8T[8][33]          @ 15360  (264)
//   bias_s[512]          @ 15624  (512)
#define USTRH    584
#define ASTR     116
#define A_OFF    9344
#define IDX_OFF  13056
#define WGT_OFF  14208
#define OUTB_OFF 9344
#define WC8_OFF  15360
#define BIAS_OFF 15624
#define SMEM_FLOATS 16136
#define SMEM_BYTES  (SMEM_FLOATS*4)

__global__ __launch_bounds__(256, 3) void main_kernel(
    const float* __restrict__ offset, const float* __restrict__ mask,
    const float* __restrict__ wc8g,   const float* __restrict__ bias,
    float* __restrict__ out)
{
    extern __shared__ float sm[];
    __half* u_h  = (__half*)sm;
    float* A_s   = sm + A_OFF;
    int*   idx_s = (int*)(sm + IDX_OFF);
    __half2* wgt_h = (__half2*)(sm + WGT_OFF);
    float* outb  = sm + OUTB_OFF;
    float* wc8T  = sm + WC8_OFF;
    float* bias_s= sm + BIAS_OFF;

    int t     = threadIdx.x;
    int bid   = blockIdx.x;               // 1024: b(2) * 512 tiles
    int b     = bid >> 9;
    int tbase = (bid & 511) << 5;
    int h     = tbase >> 7;
    int w0    = tbase & 127;
    int w     = t >> 5;
    int l     = t & 31;

    // ---- phase 0a: wc8 (transposed), bias staging ----
    wc8T[w*33 + l] = wc8g[((b*8 + w) << 14) + tbase + l];
    bias_s[t]       = bias[t];
    bias_s[t + 256] = bias[t + 256];

    // ---- phase 0b: bilinear indices & packed fp16 weights (mask folded) ----
    for (int task = t; task < 288; task += 256) {
        int p = task & 31, k = task >> 5;
        int pix = tbase + p;
        float offy = offset[((b*18 + 2*k    ) << 14) + pix];
        float offx = offset[((b*18 + 2*k + 1) << 14) + pix];
        float mval = mask  [((b*9  + k      ) << 14) + pix];
        float py = (float)h        + (float)(k/3) - 1.f + offy;
        float px = (float)(w0 + p) + (float)(k%3) - 1.f + offx;
        float y0f = floorf(py), x0f = floorf(px);
        float ly = py - y0f, lx = px - x0f;
        int y0 = (int)y0f, x0i = (int)x0f;
        int y1 = y0 + 1, x1 = x0i + 1;
        bool vy0 = (y0 >= 0) & (y0 <= 127);
        bool vy1 = (y1 >= 0) & (y1 <= 127);
        bool vx0 = (x0i >= 0) & (x0i <= 127);
        bool vx1 = (x1 >= 0) & (x1 <= 127);
        float w00 = (1.f-ly)*(1.f-lx) * ((vy0 & vx0) ? mval : 0.f);
        float w01 = (1.f-ly)*lx       * ((vy0 & vx1) ? mval : 0.f);
        float w10 = ly*(1.f-lx)       * ((vy1 & vx0) ? mval : 0.f);
        float w11 = ly*lx             * ((vy1 & vx1) ? mval : 0.f);
        int cy0 = min(max(y0, 0), 127), cy1 = min(max(y1, 0), 127);
        int cx0 = min(max(x0i,0), 127), cx1 = min(max(x1, 0), 127);
        int b4 = (p*9 + k)*4;
        *(int4*)&idx_s[b4] = make_int4(cy0*128 + cx0, cy0*128 + cx1,
                                       cy1*128 + cx0, cy1*128 + cx1);
        __half2 h00 = __floats2half2_rn(w00, w00);
        __half2 h01 = __floats2half2_rn(w01, w01);
        __half2 h10 = __floats2half2_rn(w10, w10);
        __half2 h11 = __floats2half2_rn(w11, w11);
        uint4 wv;
        wv.x = *(uint32_t*)&h00; wv.y = *(uint32_t*)&h01;
        wv.z = *(uint32_t*)&h10; wv.w = *(uint32_t*)&h11;
        *(uint4*)&wgt_h[b4] = wv;
    }
    __syncthreads();

    // ---- phase 0c: A[p][k*12+k2] = sum_g wc8[g] * M_g  (stride ASTR=116) ----
    for (int e = t; e < 2592; e += 256) {
        int p = e & 31, kk = e >> 5;
        int k = kk / 9, k2 = kk - k*9;
        float a = 0.f;
        #pragma unroll
        for (int g = 0; g < 8; g++) a += wc8T[g*33 + p] * g_Mg[g*81 + kk];
        A_s[p*ASTR + k*12 + k2] = a;
    }
    __syncthreads();

    // ---- phase 1: fp16 gather + HFMA2 bilinear + fp32 tap transform -> u_h ----
    {
        const __half2* ib = (const __half2*)g_nhwc_h + ((size_t)b << 19);  // b * 16384 * 32 half2
        const int4* idx4 = (const int4*)idx_s;
        const uint4* wgt4 = (const uint4*)wgt_h;
        int pos = (l & 3)*16 + (l >> 3)*4 + ((l >> 2) & 1)*2;
        #pragma unroll
        for (int pp = 0; pp < 4; pp++) {
            int p = w*4 + pp;
            float2 ua[9];
            #pragma unroll
            for (int i = 0; i < 9; i++) { ua[i].x = 0.f; ua[i].y = 0.f; }
            #pragma unroll
            for (int k = 0; k < 9; k++) {
                int4  id = idx4[p*9 + k];
                uint4 wq = wgt4[p*9 + k];
                __half2 w00 = *(__half2*)&wq.x;
                __half2 w01 = *(__half2*)&wq.y;
                __half2 w10 = *(__half2*)&wq.z;
                __half2 w11 = *(__half2*)&wq.w;
                __half2 vh = __hmul2(ib[id.x*32 + l], w00);
                vh = __hfma2(ib[id.y*32 + l], w01, vh);
                vh = __hfma2(ib[id.z*32 + l], w10, vh);
                vh = __hfma2(ib[id.w*32 + l], w11, vh);
                float vx = __low2float(vh);
                float vy = __high2float(vh);
                const float* Ab = A_s + p*ASTR + k*12;
                float4 a0 = *(const float4*)(Ab);
                float4 a1 = *(const float4*)(Ab + 4);
                float  a8 = Ab[8];
                ua[0].x += a0.x*vx; ua[0].y += a0.x*vy;
                ua[1].x += a0.y*vx; ua[1].y += a0.y*vy;
                ua[2].x += a0.z*vx; ua[2].y += a0.z*vy;
                ua[3].x += a0.w*vx; ua[3].y += a0.w*vy;
                ua[4].x += a1.x*vx; ua[4].y += a1.x*vy;
                ua[5].x += a1.y*vx; ua[5].y += a1.y*vy;
                ua[6].x += a1.z*vx; ua[6].y += a1.z*vy;
                ua[7].x += a1.w*vx; ua[7].y += a1.w*vy;
                ua[8].x += a8  *vx; ua[8].y += a8  *vy;
            }
            __half* urow = u_h + p*USTRH;
            #pragma unroll
            for (int k2 = 0; k2 < 9; k2++) {
                *(__half2*)(urow + k2*64 + pos) = __floats2half2_rn(ua[k2].x, ua[k2].y);
            }
        }
    }
    __syncthreads();

    // ---- phase 2: fp16 MMA  D[32px x 64o] = u[32 x 576] * W[576 x 64]  (no barriers) ----
    int m0  = (w & 1) * 16;
    int n0i = w >> 1;
    int g   = l >> 2;
    int tq  = l & 3;
    const __half* uR0 = u_h + (m0 + g)*USTRH + tq*16;
    const __half* uR1 = uR0 + 8*USTRH;
    const __half* Bb  = g_wtf + n0i*1024 + l*8;   // [slab][n0i][q][lane][8h]

    float acc[2][4];
    #pragma unroll
    for (int j = 0; j < 2; j++)
        #pragma unroll
        for (int i = 0; i < 4; i++) acc[j][i] = 0.f;

    #pragma unroll
    for (int ch = 0; ch < 9; ch++) {
        uint32_t Ag0[8], Ag1[8], Bw[16];
        *(uint4*)(Ag0)     = *(const uint4*)(uR0 + ch*64);
        *(uint4*)(Ag0 + 4) = *(const uint4*)(uR0 + ch*64 + 8);
        *(uint4*)(Ag1)     = *(const uint4*)(uR1 + ch*64);
        *(uint4*)(Ag1 + 4) = *(const uint4*)(uR1 + ch*64 + 8);
        const __half* Bc = Bb + ch*4096;
        *(uint4*)(Bw)      = *(const uint4*)(Bc);
        *(uint4*)(Bw + 4)  = *(const uint4*)(Bc + 256);
        *(uint4*)(Bw + 8)  = *(const uint4*)(Bc + 512);
        *(uint4*)(Bw + 12) = *(const uint4*)(Bc + 768);
        #pragma unroll
        for (int s = 0; s < 4; s++) {
            uint32_t a0 = Ag0[s*2], a2 = Ag0[s*2+1];
            uint32_t a1 = Ag1[s*2], a3 = Ag1[s*2+1];
            #pragma unroll
            for (int j = 0; j < 2; j++) {
                uint32_t b0 = Bw[j*8 + s*2], b1 = Bw[j*8 + s*2 + 1];
                asm volatile(
                    "mma.sync.aligned.m16n8k16.row.col.f32.f16.f16.f32 "
                    "{%0,%1,%2,%3}, {%4,%5,%6,%7}, {%8,%9}, {%0,%1,%2,%3};\n"
                    : "+f"(acc[j][0]), "+f"(acc[j][1]), "+f"(acc[j][2]), "+f"(acc[j][3])
                    : "r"(a0), "r"(a1), "r"(a2), "r"(a3), "r"(b0), "r"(b1));
            }
        }
    }

    // ---- epilogue: hoist wc8, stage D in smem, coalesced NCHW store + bias ----
    float wc8r[8];
    #pragma unroll
    for (int gg = 0; gg < 8; gg++) wc8r[gg] = wc8T[gg*33 + l];
    __syncthreads();
    #pragma unroll
    for (int j = 0; j < 2; j++) {
        int o = n0i*16 + j*8 + 2*tq;
        outb[(o    )*33 + m0 + g    ] = acc[j][0];
        outb[(o + 1)*33 + m0 + g    ] = acc[j][1];
        outb[(o    )*33 + m0 + g + 8] = acc[j][2];
        outb[(o + 1)*33 + m0 + g + 8] = acc[j][3];
    }
    __syncthreads();
    #pragma unroll
    for (int r = 0; r < 8; r++) {
        int o = r*8 + w;       // constant per warp
        float be = 0.f;
        #pragma unroll
        for (int gg = 0; gg < 8; gg++) be += wc8r[gg] * bias_s[gg*64 + o];
        out[((b*64 + o) << 14) + tbase + l] = outb[o*33 + l] + be;
    }
}

// ---------------- launch ----------------
extern "C" void kernel_launch(void* const* d_in, const int* in_sizes, int n_in,
                              void* d_out, int out_size) {
    const float* input  = (const float*)d_in[0];
    const float* offset = (const float*)d_in[1];
    const float* maskp  = (const float*)d_in[2];
    const float* w_c8   = (const float*)d_in[3];
    const float* weight = (const float*)d_in[4];
    const float* bias   = (const float*)d_in[5];
    const float* fc_w   = (const float*)d_in[6];
    const float* fc_b   = (const float*)d_in[7];
    float* out = (float*)d_out;

    cudaFuncSetAttribute(main_kernel, cudaFuncAttributeMaxDynamicSharedMemorySize, SMEM_BYTES);

    nhwc_kernel <<<1168, 256>>>(input, weight);
    setup_kernel<<<1, 256>>>(fc_w, fc_b);
    main_kernel <<<1024, 256, SMEM_BYTES>>>(offset, maskp, w_c8, bias, out);
}